// round 2
// baseline (speedup 1.0000x reference)
#include <cuda_runtime.h>
#include <math.h>

#define E_ 4
#define B_ 8
#define NS_ 3
#define NP_ 96
#define H_ 1024
#define OUT_ 4096
#define NQ_ 144
#define FFH_ 4096

__device__ __constant__ int c_SQ[3] = {64, 48, 32};
__device__ __constant__ int c_L[3]  = {320, 304, 288};
__device__ __constant__ int c_QO[3] = {0, 64, 112};
__device__ __constant__ int c_IO[3] = {0, 256, 512};

// ---------------- scratch (device globals; no allocations allowed) ----------
__device__ float g_gates[B_ * E_];
__device__ float g_x  [NP_ * 64L * H_];     // query-token state (also final y)
__device__ float g_xn [NP_ * 64L * H_];     // LN(x) / attention ctx scratch
__device__ float g_kv0[NP_ * 320L * H_];
__device__ float g_kvn[NP_ * 320L * H_];
__device__ float g_q  [NP_ * 64L * H_];
__device__ float g_k  [NP_ * 320L * H_];
__device__ float g_v  [NP_ * 320L * H_];
__device__ float g_h  [NP_ * 64L * FFH_];
__device__ float g_comb[B_ * (long)NQ_ * OUT_];

__device__ __forceinline__ float* bufptr(int id) {
    switch (id) {
        case 0: return g_x;  case 1: return g_xn; case 2: return g_kv0;
        case 3: return g_kvn; case 4: return g_q; case 5: return g_k;
        case 6: return g_v;  default: return g_h;
    }
}
__device__ __forceinline__ long bufstride(int id) {
    switch (id) {
        case 0: case 1: case 4: return 64L * H_;
        case 7: return 64L * FFH_;
        default: return 320L * H_;
    }
}

// ---------------- block reductions (256 threads) -----------------------------
__device__ __forceinline__ float blockReduceSum(float v, float* sbuf) {
    int t = threadIdx.x;
    for (int o = 16; o; o >>= 1) v += __shfl_down_sync(0xffffffffu, v, o);
    if ((t & 31) == 0) sbuf[t >> 5] = v;
    __syncthreads();
    if (t < 8) {
        v = sbuf[t];
        for (int o = 4; o; o >>= 1) v += __shfl_down_sync(0xffu, v, o);
        if (t == 0) sbuf[0] = v;
    }
    __syncthreads();
    float r = sbuf[0];
    __syncthreads();
    return r;
}
__device__ __forceinline__ float blockReduceMax(float v, float* sbuf) {
    int t = threadIdx.x;
    for (int o = 16; o; o >>= 1) v = fmaxf(v, __shfl_down_sync(0xffffffffu, v, o));
    if ((t & 31) == 0) sbuf[t >> 5] = v;
    __syncthreads();
    if (t < 8) {
        v = sbuf[t];
        for (int o = 4; o; o >>= 1) v = fmaxf(v, __shfl_down_sync(0xffu, v, o));
        if (t == 0) sbuf[0] = v;
    }
    __syncthreads();
    float r = sbuf[0];
    __syncthreads();
    return r;
}

// ---------------- gating -----------------------------------------------------
__global__ void gate_kernel(const float* __restrict__ img,
                            const int* __restrict__ task_ids,
                            const int* __restrict__ elem_ids,
                            const float* __restrict__ task_emb,
                            const float* __restrict__ elem_emb,
                            const float* __restrict__ glw,
                            const float* __restrict__ glb,
                            const float* __restrict__ gw,
                            const float* __restrict__ gb) {
    int b = blockIdx.x;
    int t = threadIdx.x;
    __shared__ float gi[1536];
    __shared__ float sn[1536];
    __shared__ float red[32];
    __shared__ float lg[4];

    // mean over 576 image tokens
    float acc0 = 0.f, acc1 = 0.f, acc2 = 0.f, acc3 = 0.f;
    const float* ib = img + (long)b * 576 * H_;
    for (int r = 0; r < 576; r++) {
        const float* row = ib + (long)r * H_;
        acc0 += row[t];        acc1 += row[t + 256];
        acc2 += row[t + 512];  acc3 += row[t + 768];
    }
    const float inv576 = 1.f / 576.f;
    gi[t]       = acc0 * inv576;  gi[t + 256] = acc1 * inv576;
    gi[t + 512] = acc2 * inv576;  gi[t + 768] = acc3 * inv576;
    gi[1024 + t] = task_emb[task_ids[b] * 256 + t];
    gi[1280 + t] = elem_emb[elem_ids[b] * 256 + t];
    __syncthreads();

    float s1 = 0.f;
    for (int d = t; d < 1536; d += 256) s1 += gi[d];
    s1 = blockReduceSum(s1, red);
    float m = s1 / 1536.f;
    float s2 = 0.f;
    for (int d = t; d < 1536; d += 256) { float dd = gi[d] - m; s2 += dd * dd; }
    s2 = blockReduceSum(s2, red);
    float rs = rsqrtf(s2 / 1536.f + 1e-5f);
    for (int d = t; d < 1536; d += 256) sn[d] = (gi[d] - m) * rs * glw[d] + glb[d];
    __syncthreads();

    for (int e = 0; e < 4; e++) {
        float pd = 0.f;
        for (int d = t; d < 1536; d += 256) pd += sn[d] * gw[e * 1536 + d];
        pd = blockReduceSum(pd, red);
        if (t == 0) {
            float l = pd + gb[e];
            lg[e] = fminf(fmaxf(l, -15.f), 15.f);
        }
        __syncthreads();
    }
    if (t == 0) {
        float mx = fmaxf(fmaxf(lg[0], lg[1]), fmaxf(lg[2], lg[3]));
        float pe[4]; float den = 0.f;
        for (int e = 0; e < 4; e++) { pe[e] = expf(lg[e] - mx); den += pe[e]; }
        for (int e = 0; e < 4; e++) pe[e] /= den;
        int i1 = 0;
        for (int e = 1; e < 4; e++) if (pe[e] > pe[i1]) i1 = e;
        int i2 = -1;
        for (int e = 0; e < 4; e++) {
            if (e == i1) continue;
            if (i2 < 0 || pe[e] > pe[i2]) i2 = e;
        }
        float sum2 = pe[i1] + pe[i2] + 1e-9f;
        for (int e = 0; e < 4; e++) g_gates[b * 4 + e] = 0.f;
        g_gates[b * 4 + i1] = pe[i1] / sum2;
        g_gates[b * 4 + i2] = pe[i2] / sum2;
    }
}

// ---------------- build kv0 + init x -----------------------------------------
__global__ void build_kernel(const float* __restrict__ query,
                             const float* __restrict__ img,
                             const float* __restrict__ pp) {
    int p = blockIdx.y;
    int e = p / 24, r = p % 24, b = r / 3, s = r % 3;
    if (g_gates[b * 4 + e] == 0.f) return;
    int tk = blockIdx.x;
    int L = c_L[s];
    if (tk >= L) return;
    int sq = c_SQ[s];
    const float* src;
    if (tk < sq) {
        src = query + ((long)e * NQ_ + c_QO[s] + tk) * H_;
    } else {
        int j = c_IO[s] + tk - sq;
        src = (j < 576) ? img + ((long)b * 576 + j) * H_
                        : pp  + ((long)b * 192 + (j - 576)) * H_;
    }
    float* dst = g_kv0 + (long)p * 320 * H_ + (long)tk * H_;
    int t = threadIdx.x;
    float v0 = src[t], v1 = src[t + 256], v2 = src[t + 512], v3 = src[t + 768];
    dst[t] = v0; dst[t + 256] = v1; dst[t + 512] = v2; dst[t + 768] = v3;
    if (tk < sq) {
        float* xd = g_x + (long)p * 64 * H_ + (long)tk * H_;
        xd[t] = v0; xd[t + 256] = v1; xd[t + 512] = v2; xd[t + 768] = v3;
    }
}

// ---------------- row LayerNorm ----------------------------------------------
__global__ void ln_rows(int src, int dst,
                        const float* __restrict__ wbase,
                        const float* __restrict__ bbase,
                        int m_is_L, int layer) {
    int p = blockIdx.y;
    int e = p / 24, r = p % 24, b = r / 3, s = r % 3;
    if (g_gates[b * 4 + e] == 0.f) return;
    int M = m_is_L ? c_L[s] : c_SQ[s];
    int row = blockIdx.x;
    if (row >= M) return;
    const float* x = bufptr(src) + (long)p * bufstride(src) + (long)row * H_;
    float* y       = bufptr(dst) + (long)p * bufstride(dst) + (long)row * H_;
    const float* w  = wbase + (long)(e * 2 + layer) * H_;
    const float* bb = bbase + (long)(e * 2 + layer) * H_;
    __shared__ float sx[1024];
    __shared__ float red[32];
    int t = threadIdx.x;
    float s1 = 0.f;
    #pragma unroll
    for (int j = 0; j < 4; j++) { float v = x[t + j * 256]; sx[t + j * 256] = v; s1 += v; }
    s1 = blockReduceSum(s1, red);
    float m = s1 / 1024.f;
    float s2 = 0.f;
    #pragma unroll
    for (int j = 0; j < 4; j++) { float d = sx[t + j * 256] - m; s2 += d * d; }
    s2 = blockReduceSum(s2, red);
    float rs = rsqrtf(s2 / 1024.f + 1e-5f);
    #pragma unroll
    for (int j = 0; j < 4; j++) {
        int d = t + j * 256;
        y[d] = (sx[d] - m) * rs * w[d] + bb[d];
    }
}

// ---------------- generic GEMM: C[M,N] = A[M,K] @ W[N,K]^T + bias ------------
struct GArgs {
    int a_id; int c_id;
    const float* W;    long w_stride;     // per (e,layer)
    const float* bias; long bias_stride;  // per (e,layer)
    const float* ls;                      // per (e,layer), stride H_; epi==2 only
    int N; int K;
    int m_is_L;  // M = L[s] else SQ[s]
    int epi;     // 0 store, 1 gelu-store, 2 C += ls*(c+bias) (residual)
    int layer;
};

__global__ void gemm_k(GArgs g) {
    int p = blockIdx.z;
    int e = p / 24, r = p % 24, b = r / 3, s = r % 3;
    if (g_gates[b * 4 + e] == 0.f) return;
    int M = g.m_is_L ? c_L[s] : c_SQ[s];
    int m0 = blockIdx.x * 64;
    if (m0 >= M) return;
    int n0 = blockIdx.y * 64;
    const float* A    = bufptr(g.a_id) + (long)p * bufstride(g.a_id);
    const float* W    = g.W    + (long)(e * 2 + g.layer) * g.w_stride;
    const float* bias = g.bias + (long)(e * 2 + g.layer) * g.bias_stride;
    float* C          = bufptr(g.c_id) + (long)p * bufstride(g.c_id);

    __shared__ float As[16][64];
    __shared__ float Ws[16][64];
    int t = threadIdx.x;
    int lrow = t >> 2, kq = (t & 3) << 2;
    int ty = t >> 4, tx = t & 15;
    float c[4][4];
    #pragma unroll
    for (int i = 0; i < 4; i++)
        #pragma unroll
        for (int j = 0; j < 4; j++) c[i][j] = 0.f;

    int am = m0 + lrow;
    bool aval = am < M;
    const float* arow = A + (long)am * g.K;
    const float* wrow = W + (long)(n0 + lrow) * g.K;

    for (int k0 = 0; k0 < g.K; k0 += 16) {
        float4 av = make_float4(0.f, 0.f, 0.f, 0.f);
        if (aval) av = *(const float4*)(arow + k0 + kq);
        float4 wv = *(const float4*)(wrow + k0 + kq);
        __syncthreads();
        As[kq + 0][lrow] = av.x; As[kq + 1][lrow] = av.y;
        As[kq + 2][lrow] = av.z; As[kq + 3][lrow] = av.w;
        Ws[kq + 0][lrow] = wv.x; Ws[kq + 1][lrow] = wv.y;
        Ws[kq + 2][lrow] = wv.z; Ws[kq + 3][lrow] = wv.w;
        __syncthreads();
        #pragma unroll
        for (int kk = 0; kk < 16; kk++) {
            float a0 = As[kk][ty * 4 + 0], a1 = As[kk][ty * 4 + 1];
            float a2 = As[kk][ty * 4 + 2], a3 = As[kk][ty * 4 + 3];
            float b0 = Ws[kk][tx * 4 + 0], b1 = Ws[kk][tx * 4 + 1];
            float b2 = Ws[kk][tx * 4 + 2], b3 = Ws[kk][tx * 4 + 3];
            c[0][0] += a0 * b0; c[0][1] += a0 * b1; c[0][2] += a0 * b2; c[0][3] += a0 * b3;
            c[1][0] += a1 * b0; c[1][1] += a1 * b1; c[1][2] += a1 * b2; c[1][3] += a1 * b3;
            c[2][0] += a2 * b0; c[2][1] += a2 * b1; c[2][2] += a2 * b2; c[2][3] += a2 * b3;
            c[3][0] += a3 * b0; c[3][1] += a3 * b1; c[3][2] += a3 * b2; c[3][3] += a3 * b3;
        }
    }

    const float* lsp = (g.epi == 2) ? (g.ls + (long)(e * 2 + g.layer) * H_) : nullptr;
    #pragma unroll
    for (int i = 0; i < 4; i++) {
        int m = m0 + ty * 4 + i;
        if (m >= M) continue;
        #pragma unroll
        for (int j = 0; j < 4; j++) {
            int n = n0 + tx * 4 + j;
            float v = c[i][j] + bias[n];
            long idx = (long)m * g.N + n;
            if (g.epi == 0) {
                C[idx] = v;
            } else if (g.epi == 1) {
                C[idx] = v * 0.5f * (1.f + erff(v * 0.70710678118654752f));
            } else {
                C[idx] += lsp[n] * v;
            }
        }
    }
}

// ---------------- attention (per problem, head, q-row) -----------------------
__global__ void attn_kernel() {
    int p = blockIdx.z;
    int e = p / 24, r = p % 24, b = r / 3, s = r % 3;
    if (g_gates[b * 4 + e] == 0.f) return;
    int sq = c_SQ[s];
    int row = blockIdx.x;
    if (row >= sq) return;
    int L = c_L[s];
    int h = blockIdx.y;
    int t = threadIdx.x;

    __shared__ float sc[320];
    __shared__ float qv[64];
    __shared__ float red[32];
    __shared__ float cbuf[4][64];

    const float* Q = g_q + (long)p * 64 * H_ + (long)row * H_ + h * 64;
    const float* K = g_k + (long)p * 320 * H_ + h * 64;
    const float* V = g_v + (long)p * 320 * H_ + h * 64;

    if (t < 64) qv[t] = Q[t];
    __syncthreads();

    for (int k = t; k < L; k += 256) {
        const float* kr = K + (long)k * H_;
        float d = 0.f;
        #pragma unroll
        for (int dd = 0; dd < 64; dd++) d += qv[dd] * kr[dd];
        sc[k] = d * 0.125f;
    }
    __syncthreads();

    float mx = -1e30f;
    for (int k = t; k < L; k += 256) mx = fmaxf(mx, sc[k]);
    mx = blockReduceMax(mx, red);
    float sum = 0.f;
    for (int k = t; k < L; k += 256) { float ev = expf(sc[k] - mx); sc[k] = ev; sum += ev; }
    sum = blockReduceSum(sum, red);
    float inv = 1.f / sum;

    int d = t & 63, ch = t >> 6;
    float acc = 0.f;
    for (int k = ch; k < L; k += 4) acc += sc[k] * V[(long)k * H_ + d];
    cbuf[ch][d] = acc;
    __syncthreads();
    if (t < 64) {
        float o = (cbuf[0][t] + cbuf[1][t] + cbuf[2][t] + cbuf[3][t]) * inv;
        g_xn[(long)p * 64 * H_ + (long)row * H_ + h * 64 + t] = o;
    }
}

// ---------------- expert-weighted output projection --------------------------
__global__ void out_gemm(const float* __restrict__ outp_w,
                         const float* __restrict__ outp_b) {
    int b = blockIdx.z;
    int m0 = blockIdx.x * 64;   // over 144 query rows
    int n0 = blockIdx.y * 64;   // over 4096 outputs
    __shared__ float As[16][64];
    __shared__ float Ws[16][64];
    int t = threadIdx.x;
    int lrow = t >> 2, kq = (t & 3) << 2;
    int ty = t >> 4, tx = t & 15;

    int qg = m0 + lrow;
    bool aval = qg < NQ_;
    int s = 0, lr = 0;
    if (aval) {
        s = (qg < 64) ? 0 : ((qg < 112) ? 1 : 2);
        lr = qg - c_QO[s];
    }

    float tot[4][4];
    #pragma unroll
    for (int i = 0; i < 4; i++)
        #pragma unroll
        for (int j = 0; j < 4; j++) tot[i][j] = 0.f;

    for (int e = 0; e < 4; e++) {
        float gt = g_gates[b * 4 + e];
        if (gt == 0.f) continue;
        const float* A = g_x + ((long)(e * 24 + b * 3 + s) * 64 + lr) * H_;
        const float* W = outp_w + (long)e * OUT_ * H_ + (long)(n0 + lrow) * H_;
        float c[4][4];
        #pragma unroll
        for (int i = 0; i < 4; i++)
            #pragma unroll
            for (int j = 0; j < 4; j++) c[i][j] = 0.f;
        for (int k0 = 0; k0 < H_; k0 += 16) {
            float4 av = make_float4(0.f, 0.f, 0.f, 0.f);
            if (aval) av = *(const float4*)(A + k0 + kq);
            float4 wv = *(const float4*)(W + k0 + kq);
            __syncthreads();
            As[kq + 0][lrow] = av.x; As[kq + 1][lrow] = av.y;
            As[kq + 2][lrow] = av.z; As[kq + 3][lrow] = av.w;
            Ws[kq + 0][lrow] = wv.x; Ws[kq + 1][lrow] = wv.y;
            Ws[kq + 2][lrow] = wv.z; Ws[kq + 3][lrow] = wv.w;
            __syncthreads();
            #pragma unroll
            for (int kk = 0; kk < 16; kk++) {
                float a0 = As[kk][ty * 4 + 0], a1 = As[kk][ty * 4 + 1];
                float a2 = As[kk][ty * 4 + 2], a3 = As[kk][ty * 4 + 3];
                float b0 = Ws[kk][tx * 4 + 0], b1 = Ws[kk][tx * 4 + 1];
                float b2 = Ws[kk][tx * 4 + 2], b3 = Ws[kk][tx * 4 + 3];
                c[0][0] += a0 * b0; c[0][1] += a0 * b1; c[0][2] += a0 * b2; c[0][3] += a0 * b3;
                c[1][0] += a1 * b0; c[1][1] += a1 * b1; c[1][2] += a1 * b2; c[1][3] += a1 * b3;
                c[2][0] += a2 * b0; c[2][1] += a2 * b1; c[2][2] += a2 * b2; c[2][3] += a2 * b3;
                c[3][0] += a3 * b0; c[3][1] += a3 * b1; c[3][2] += a3 * b2; c[3][3] += a3 * b3;
            }
        }
        const float* bias = outp_b + (long)e * OUT_;
        #pragma unroll
        for (int i = 0; i < 4; i++)
            #pragma unroll
            for (int j = 0; j < 4; j++)
                tot[i][j] += gt * (c[i][j] + bias[n0 + tx * 4 + j]);
    }

    #pragma unroll
    for (int i = 0; i < 4; i++) {
        int m = m0 + ty * 4 + i;
        if (m >= NQ_) continue;
        #pragma unroll
        for (int j = 0; j < 4; j++) {
            int n = n0 + tx * 4 + j;
            g_comb[((long)b * NQ_ + m) * OUT_ + n] = tot[i][j];
        }
    }
}

// ---------------- final RMS + scaling ----------------------------------------
__global__ void rms_kernel(const float* __restrict__ final_w,
                           const float* __restrict__ out_gain,
                           float* __restrict__ out) {
    int q = blockIdx.x, b = blockIdx.y;
    int t = threadIdx.x;
    const float* c = g_comb + ((long)b * NQ_ + q) * OUT_;
    float s2 = 0.f;
    for (int o = t; o < OUT_; o += 256) { float v = c[o]; s2 += v * v; }
    __shared__ float red[32];
    s2 = blockReduceSum(s2, red);
    float rs = rsqrtf(s2 / (float)OUT_ + 1e-6f);
    float* orow = out + ((long)b * NQ_ + q) * OUT_;
    for (int o = t; o < OUT_; o += 256) orow[o] = c[o] * rs * final_w[o] * out_gain[o];
}

// ---------------- host driver ------------------------------------------------
extern "C" void kernel_launch(void* const* d_in, const int* in_sizes, int n_in,
                              void* d_out, int out_size) {
    const float* image_embs = (const float*)d_in[0];
    const float* phys       = (const float*)d_in[1];
    const int*   task_ids   = (const int*)d_in[2];
    const int*   elem_ids   = (const int*)d_in[3];
    const float* query      = (const float*)d_in[4];
    const float* ln1_w      = (const float*)d_in[5];
    const float* ln1_b      = (const float*)d_in[6];
    const float* ln1kv_w    = (const float*)d_in[7];
    const float* ln1kv_b    = (const float*)d_in[8];
    const float* attn_in_w  = (const float*)d_in[9];
    const float* attn_in_b  = (const float*)d_in[10];
    const float* attn_out_w = (const float*)d_in[11];
    const float* attn_out_b = (const float*)d_in[12];
    const float* ls1        = (const float*)d_in[13];
    const float* ls2        = (const float*)d_in[14];
    const float* ln2_w      = (const float*)d_in[15];
    const float* ln2_b      = (const float*)d_in[16];
    const float* fc_w       = (const float*)d_in[17];
    const float* fc_b       = (const float*)d_in[18];
    const float* proj_w     = (const float*)d_in[19];
    const float* proj_b     = (const float*)d_in[20];
    const float* outp_w     = (const float*)d_in[21];
    const float* outp_b     = (const float*)d_in[22];
    const float* task_emb   = (const float*)d_in[23];
    const float* elem_emb   = (const float*)d_in[24];
    const float* gate_ln_w  = (const float*)d_in[25];
    const float* gate_ln_b  = (const float*)d_in[26];
    const float* gate_w     = (const float*)d_in[27];
    const float* gate_b     = (const float*)d_in[28];
    const float* output_gain= (const float*)d_in[29];
    const float* final_w    = (const float*)d_in[30];
    (void)in_sizes; (void)n_in; (void)out_size;

    gate_kernel<<<B_, 256>>>(image_embs, task_ids, elem_ids, task_emb, elem_emb,
                             gate_ln_w, gate_ln_b, gate_w, gate_b);
    build_kernel<<<dim3(320, NP_), 256>>>(query, image_embs, phys);

    for (int l = 0; l < 2; l++) {
        ln_rows<<<dim3(320, NP_), 256>>>(2, 3, ln1kv_w, ln1kv_b, 1, l);
        ln_rows<<<dim3(64, NP_), 256>>>(0, 1, ln1_w, ln1_b, 0, l);

        GArgs gq = {};
        gq.a_id = 1; gq.c_id = 4;
        gq.W = attn_in_w; gq.w_stride = 3072L * 1024;
        gq.bias = attn_in_b; gq.bias_stride = 3072;
        gq.ls = nullptr; gq.N = 1024; gq.K = 1024;
        gq.m_is_L = 0; gq.epi = 0; gq.layer = l;
        gemm_k<<<dim3(1, 16, NP_), 256>>>(gq);

        GArgs gk = gq;
        gk.a_id = 3; gk.c_id = 5;
        gk.W = attn_in_w + 1024L * 1024; gk.bias = attn_in_b + 1024;
        gk.m_is_L = 1;
        gemm_k<<<dim3(5, 16, NP_), 256>>>(gk);

        GArgs gv = gk;
        gv.c_id = 6;
        gv.W = attn_in_w + 2048L * 1024; gv.bias = attn_in_b + 2048;
        gemm_k<<<dim3(5, 16, NP_), 256>>>(gv);

        attn_kernel<<<dim3(64, 16, NP_), 256>>>();

        GArgs go = {};
        go.a_id = 1; go.c_id = 0;
        go.W = attn_out_w; go.w_stride = 1024L * 1024;
        go.bias = attn_out_b; go.bias_stride = 1024;
        go.ls = ls1; go.N = 1024; go.K = 1024;
        go.m_is_L = 0; go.epi = 2; go.layer = l;
        gemm_k<<<dim3(1, 16, NP_), 256>>>(go);

        ln_rows<<<dim3(64, NP_), 256>>>(0, 1, ln2_w, ln2_b, 0, l);

        GArgs gf = {};
        gf.a_id = 1; gf.c_id = 7;
        gf.W = fc_w; gf.w_stride = 4096L * 1024;
        gf.bias = fc_b; gf.bias_stride = 4096;
        gf.ls = nullptr; gf.N = 4096; gf.K = 1024;
        gf.m_is_L = 0; gf.epi = 1; gf.layer = l;
        gemm_k<<<dim3(1, 64, NP_), 256>>>(gf);

        GArgs gp = {};
        gp.a_id = 7; gp.c_id = 0;
        gp.W = proj_w; gp.w_stride = 1024L * 4096;
        gp.bias = proj_b; gp.bias_stride = 1024;
        gp.ls = ls2; gp.N = 1024; gp.K = 4096;
        gp.m_is_L = 0; gp.epi = 2; gp.layer = l;
        gemm_k<<<dim3(1, 16, NP_), 256>>>(gp);
    }

    out_gemm<<<dim3(3, 64, B_), 256>>>(outp_w, outp_b);
    rms_kernel<<<dim3(NQ_, B_), 256>>>(final_w, output_gain, (float*)d_out);
}